// round 9
// baseline (speedup 1.0000x reference)
#include <cuda_runtime.h>

// BurstSnn: burst encoder + 2-layer LIF SNN, 32 timesteps.
// x [B,187] f32, W1 [50,187] f32, W2 [5,50] f32
// out: spk_rec [32,B,5] f32 then counts [B] f32
//
// Two samples/warp (16-lane halves). Sparse event processing both layers.
// t=0,1 peeled with COMPLEMENT accumulation (colsum - nonspikers).
// Main loop t>=2: sparse events + exact 2-consecutive-empty death (prevz).
// spk_rec zeroed IN-KERNEL by each warp for its own samples (no memset node);
// kernel then stores only 1.0s and breaks at quiescence.

#define T_STEPS 32
#define DDIM 187
#define HDIM 50
#define CDIM 5
#define NGRP 12
#define W1PAD 52          // floats per W1 row (208 B)
#define W1TAIL 16
#define W2PAD 68          // 272 B rows

__device__ __forceinline__ void addx2(unsigned long long &a, unsigned long long b) {
    asm("add.rn.f32x2 %0, %1, %2;" : "=l"(a) : "l"(a), "l"(b));
}
__device__ __forceinline__ void mulx2(unsigned long long &a, unsigned long long b) {
    asm("mul.rn.f32x2 %0, %1, %2;" : "=l"(a) : "l"(a), "l"(b));
}
__device__ __forceinline__ unsigned long long packx2(float lo, float hi) {
    unsigned long long r; asm("mov.b64 %0, {%1,%2};" : "=l"(r) : "f"(lo), "f"(hi)); return r;
}
__device__ __forceinline__ void unpackx2(unsigned long long v, float &lo, float &hi) {
    asm("mov.b64 {%0,%1}, %2;" : "=f"(lo), "=f"(hi) : "l"(v));
}

// pair-unrolled event accumulation over set bits of mh (warp-lockstep loop)
__device__ __forceinline__ void ev_accum(unsigned mh, const char* gb,
                                         unsigned long long &A01,
                                         unsigned long long &A23) {
    while (mh) {
        int i0 = __ffs(mh) - 1; mh &= mh - 1;
        const ulonglong2 w0 = *(const ulonglong2*)(gb + i0 * 208);
        if (mh) {
            int i1 = __ffs(mh) - 1; mh &= mh - 1;
            const ulonglong2 w1 = *(const ulonglong2*)(gb + i1 * 208);
            addx2(A01, w0.x); addx2(A23, w0.y);
            addx2(A01, w1.x); addx2(A23, w1.y);
        } else {
            addx2(A01, w0.x); addx2(A23, w0.y);
        }
    }
}

// layer-2 sparse gather + LIF2 + store; returns (anyS1|anyS2) for quiescence
__device__ __forceinline__ unsigned step_tail(bool s0, bool s1, bool s2, bool s3,
                                              int hl, int shamt,
                                              const float* __restrict__ w2b,
                                              float &m2, bool valid,
                                              float* &po, size_t tstride4) {
    unsigned b0 = __ballot_sync(0xffffffffu, s0);
    unsigned b1 = __ballot_sync(0xffffffffu, s1);
    unsigned b2 = __ballot_sync(0xffffffffu, s2);
    unsigned b3 = __ballot_sync(0xffffffffu, s3);
    unsigned anyS1 = b0 | b1 | b2 | b3;
    float cur2 = 0.0f;
    if (anyS1) {
        unsigned f;
        f = (b0 >> shamt) & 0xffffu;
        while (f) { int i = __ffs(f) - 1; f &= f - 1;
                    if (hl < CDIM) cur2 += w2b[4 * i + 0]; }
        f = (b1 >> shamt) & 0xffffu;
        while (f) { int i = __ffs(f) - 1; f &= f - 1;
                    if (hl < CDIM) cur2 += w2b[4 * i + 1]; }
        f = (b2 >> shamt) & 0xffffu;
        while (f) { int i = __ffs(f) - 1; f &= f - 1;
                    if (hl < CDIM) cur2 += w2b[4 * i + 2]; }
        f = (b3 >> shamt) & 0xffffu;
        while (f) { int i = __ffs(f) - 1; f &= f - 1;
                    if (hl < CDIM) cur2 += w2b[4 * i + 3]; }
    }
    m2 = 0.9f * m2 + cur2;
    bool sp2 = (hl < CDIM) && (m2 > 1.0f);
    if (sp2) { m2 -= 1.0f; if (valid) *po = 1.0f; }
    po = (float*)((char*)po + tstride4);
    unsigned anyS2 = __ballot_sync(0xffffffffu, sp2);
    return anyS1 | anyS2;
}

__global__ __launch_bounds__(256, 5)
void burst_snn_kernel(const float* __restrict__ x,
                      const float* __restrict__ W1,
                      const float* __restrict__ W2,
                      float* __restrict__ out, int B)
{
    __shared__ __align__(16) float sW1[DDIM * W1PAD + W1TAIL];
    __shared__ float sW2[CDIM * W2PAD];
    __shared__ float sPart[4 * W1PAD];
    __shared__ __align__(16) float sCol[64];

    const int tid  = threadIdx.x;
    const int lane = tid & 31;
    const int warpg = blockIdx.x * 8 + (tid >> 5);
    const int b0w  = warpg * 2;                   // this warp's first sample

    // ---- zero this warp's spk_rec slice: lane covers timestep t = lane ----
    // 10 contiguous floats (2 samples x 5 classes). Ordering vs the later
    // sparse 1.0 stores is guaranteed by the __syncthreads below.
    if (b0w < B) {
        float* z = out + (size_t)lane * B * CDIM + (size_t)b0w * CDIM;
        int n = (b0w + 1 < B) ? 10 : 5;
#pragma unroll
        for (int k = 0; k < 10; k++)
            if (k < n) z[k] = 0.0f;
    }

    for (int i = tid; i < DDIM * W1PAD + W1TAIL; i += 256) {
        float v = 0.0f;
        if (i < DDIM * W1PAD) {
            int d = i / W1PAD, u = i - d * W1PAD;
            if (u < HDIM) v = W1[u * DDIM + d];
        }
        sW1[i] = v;
    }
    for (int i = tid; i < CDIM * W2PAD; i += 256) {
        int c = i / W2PAD, h = i - c * W2PAD;
        sW2[i] = (h < HDIM) ? W2[c * HDIM + h] : 0.0f;
    }
    __syncthreads();

    // ---- column sums of sW1 (52 padded units x 4 segments) ----
    if (tid < 4 * W1PAD) {
        int u = tid % W1PAD, seg = tid / W1PAD;
        float sa = 0.0f, sb = 0.0f;
        int d = seg;
        for (; d + 4 < DDIM; d += 8) {
            sa += sW1[d * W1PAD + u];
            sb += sW1[(d + 4) * W1PAD + u];
        }
        for (; d < DDIM; d += 4) sa += sW1[d * W1PAD + u];
        sPart[seg * W1PAD + u] = sa + sb;
    }
    __syncthreads();
    if (tid < 64) {
        float v = 0.0f;
        if (tid < W1PAD)
            v = sPart[tid] + sPart[W1PAD + tid] + sPart[2 * W1PAD + tid]
              + sPart[3 * W1PAD + tid];
        sCol[tid] = v;
    }
    __syncthreads();

    const int hl   = lane & 15;
    const int half = lane >> 4;
    const int b    = b0w + half;
    const bool valid = (b < B);

    const float INIT_TH = 0.125f;
    const unsigned long long BETA2 = packx2(0.9f, 0.9f);

    // encoder state: dim d = hl + 16*j
    float r[NGRP], th[NGRP];
    const float* xb = x + (size_t)b * DDIM;
#pragma unroll
    for (int j = 0; j < NGRP; j++) {
        int d = hl + 16 * j;
        r[j]  = (valid && d < DDIM) ? xb[d] : -1.0f;   // -1: dead from start
        th[j] = INIT_TH;
    }

    const bool v01 = (hl < 13), v23 = (hl < 12);

    unsigned long long m01, m23;                 // mem1 packed pairs
    float m2 = 0.0f;
    int cnt = 0;
    unsigned alive = 0xfffu, prevz = 0u, e0 = 0u;

    const char*  wb  = (const char*)sW1 + hl * 16;
    const float* w2b = sW2 + hl * W2PAD;
    const int shamt = lane & 16;
    float* po = out + (size_t)b * CDIM + hl;
    const size_t tstride4 = (size_t)B * CDIM * sizeof(float);

    const ulonglong2 cs = *(const ulonglong2*)((const char*)sCol + hl * 16);
    float g0, g1, g2, g3;
    unpackx2(cs.x, g0, g1); unpackx2(cs.y, g2, g3);

    // ================= t = 0 (complement: ~87% spike) =================
    {
        unsigned long long c01 = 0ull, c23 = 0ull;
#pragma unroll
        for (int j = 0; j < NGRP; j++) {
            bool s = (r[j] >= th[j]);
            unsigned bal = __ballot_sync(0xffffffffu, s);
            cnt += s;
            if (s) { r[j] -= th[j]; th[j] *= 2.0f; }     // else th stays INIT
            if (bal == 0u) e0 |= (1u << j);
            unsigned mh = ((~bal) >> shamt) & ((j == NGRP - 1) ? 0x07ffu : 0xffffu);
            ev_accum(mh, wb + j * (16 * 208), c01, c23);
        }
        float c0, c1, c2, c3;
        unpackx2(c01, c0, c1); unpackx2(c23, c2, c3);
        float a0 = g0 - c0, a1 = g1 - c1, a2 = g2 - c2, a3 = g3 - c3;
        bool s0 = v01 && (a0 > 1.0f), s1 = v01 && (a1 > 1.0f);
        bool s2 = v23 && (a2 > 1.0f), s3 = v23 && (a3 > 1.0f);
        if (s0) a0 -= 1.0f; if (s1) a1 -= 1.0f;
        if (s2) a2 -= 1.0f; if (s3) a3 -= 1.0f;
        m01 = packx2(a0, a1); m23 = packx2(a2, a3);
        step_tail(s0, s1, s2, s3, hl, shamt, w2b, m2, valid, po, tstride4);
    }

    // ================= t = 1 (complement: ~62% spike) =================
    {
        mulx2(m01, BETA2); mulx2(m23, BETA2);
        unsigned long long c01 = 0ull, c23 = 0ull;
#pragma unroll
        for (int j = 0; j < NGRP; j++) {
            bool s = (r[j] >= th[j]);
            unsigned bal = __ballot_sync(0xffffffffu, s);
            cnt += s;
            if (s) { r[j] -= th[j]; th[j] *= 2.0f; }
            else   { th[j] = INIT_TH; }
            if (bal == 0u) prevz |= (1u << j);           // empty at t=1
            unsigned mh = ((~bal) >> shamt) & ((j == NGRP - 1) ? 0x07ffu : 0xffffu);
            ev_accum(mh, wb + j * (16 * 208), c01, c23);
        }
        // dead if empty at both t0 and t1 (th reset at t0 => t1 test was exact)
        alive &= ~(e0 & prevz);
        float a0, a1, a2, a3, c0, c1, c2, c3;
        unpackx2(m01, a0, a1); unpackx2(m23, a2, a3);
        unpackx2(c01, c0, c1); unpackx2(c23, c2, c3);
        a0 += g0 - c0; a1 += g1 - c1; a2 += g2 - c2; a3 += g3 - c3;
        bool s0 = v01 && (a0 > 1.0f), s1 = v01 && (a1 > 1.0f);
        bool s2 = v23 && (a2 > 1.0f), s3 = v23 && (a3 > 1.0f);
        if (s0) a0 -= 1.0f; if (s1) a1 -= 1.0f;
        if (s2) a2 -= 1.0f; if (s3) a3 -= 1.0f;
        m01 = packx2(a0, a1); m23 = packx2(a2, a3);
        step_tail(s0, s1, s2, s3, hl, shamt, w2b, m2, valid, po, tstride4);
    }

    // ============ main loop t >= 2 (sparse + prevz exact death) ============
#pragma unroll 1
    for (int t = 2; t < T_STEPS; t++) {
        mulx2(m01, BETA2); mulx2(m23, BETA2);

#pragma unroll
        for (int j = 0; j < NGRP; j++) {
            const unsigned bit = 1u << j;
            if (!(alive & bit)) continue;
            bool s = (r[j] >= th[j]);
            unsigned bal = __ballot_sync(0xffffffffu, s);
            if (bal == 0u) {
                th[j] = INIT_TH;
                // empty twice in a row => all r < 0.125 => silent forever
                if (prevz & bit) alive &= ~bit;
                else prevz |= bit;
                continue;
            }
            prevz &= ~bit;
            cnt += s;
            if (s) { r[j] -= th[j]; th[j] *= 2.0f; }
            else   { th[j] = INIT_TH; }
            unsigned mh = (bal >> shamt) & 0xffffu;
            ev_accum(mh, wb + j * (16 * 208), m01, m23);
        }

        float a0, a1, a2, a3;
        unpackx2(m01, a0, a1); unpackx2(m23, a2, a3);
        bool s0 = v01 && (a0 > 1.0f), s1 = v01 && (a1 > 1.0f);
        bool s2 = v23 && (a2 > 1.0f), s3 = v23 && (a3 > 1.0f);
        if (s0) a0 -= 1.0f; if (s1) a1 -= 1.0f;
        if (s2) a2 -= 1.0f; if (s3) a3 -= 1.0f;
        m01 = packx2(a0, a1); m23 = packx2(a2, a3);

        unsigned any = step_tail(s0, s1, s2, s3, hl, shamt, w2b, m2,
                                 valid, po, tstride4);
        if (alive == 0u && any == 0u) break;     // provably all-zero from here
    }

    // -------- spike counts (exact integer, reduce within half) --------
#pragma unroll
    for (int off = 8; off; off >>= 1)
        cnt += __shfl_xor_sync(0xffffffffu, cnt, off);
    if (valid && hl == 0)
        out[(size_t)T_STEPS * B * CDIM + b] = (float)cnt;
}

extern "C" void kernel_launch(void* const* d_in, const int* in_sizes, int n_in,
                              void* d_out, int out_size)
{
    const float* x  = (const float*)d_in[0];
    const float* W1 = (const float*)d_in[1];
    const float* W2 = (const float*)d_in[2];
    float* out = (float*)d_out;

    int B = in_sizes[0] / DDIM;
    int blocks = (B + 15) / 16;   // 8 warps/block, 2 samples/warp
    burst_snn_kernel<<<blocks, 256>>>(x, W1, W2, out, B);
}

// round 10
// speedup vs baseline: 1.2186x; 1.2186x over previous
#include <cuda_runtime.h>

// BurstSnn: burst encoder + 2-layer LIF SNN, 32 timesteps.
// x [B,187] f32, W1 [50,187] f32, W2 [5,50] f32
// out: spk_rec [32,B,5] f32 then counts [B] f32
//
// Two samples/warp (16-lane halves). Sparse event processing both layers.
// t=0,1 peeled with COMPLEMENT accumulation (colsum - nonspikers).
// Main loop t>=2: sparse events + exact 2-consecutive-empty death (prevz).
// spk_rec pre-zeroed by cudaMemsetAsync (coalesced); kernel stores only 1.0s
// and breaks at quiescence.

#define T_STEPS 32
#define DDIM 187
#define HDIM 50
#define CDIM 5
#define NGRP 12
#define W1PAD 52          // floats per W1 row (208 B)
#define W1TAIL 16
#define W2PAD 68          // 272 B rows

__device__ __forceinline__ void addx2(unsigned long long &a, unsigned long long b) {
    asm("add.rn.f32x2 %0, %1, %2;" : "=l"(a) : "l"(a), "l"(b));
}
__device__ __forceinline__ void mulx2(unsigned long long &a, unsigned long long b) {
    asm("mul.rn.f32x2 %0, %1, %2;" : "=l"(a) : "l"(a), "l"(b));
}
__device__ __forceinline__ unsigned long long packx2(float lo, float hi) {
    unsigned long long r; asm("mov.b64 %0, {%1,%2};" : "=l"(r) : "f"(lo), "f"(hi)); return r;
}
__device__ __forceinline__ void unpackx2(unsigned long long v, float &lo, float &hi) {
    asm("mov.b64 {%0,%1}, %2;" : "=f"(lo), "=f"(hi) : "l"(v));
}

// pair-unrolled event accumulation over set bits of mh (warp-lockstep loop)
__device__ __forceinline__ void ev_accum(unsigned mh, const char* gb,
                                         unsigned long long &A01,
                                         unsigned long long &A23) {
    while (mh) {
        int i0 = __ffs(mh) - 1; mh &= mh - 1;
        const ulonglong2 w0 = *(const ulonglong2*)(gb + i0 * 208);
        if (mh) {
            int i1 = __ffs(mh) - 1; mh &= mh - 1;
            const ulonglong2 w1 = *(const ulonglong2*)(gb + i1 * 208);
            addx2(A01, w0.x); addx2(A23, w0.y);
            addx2(A01, w1.x); addx2(A23, w1.y);
        } else {
            addx2(A01, w0.x); addx2(A23, w0.y);
        }
    }
}

// layer-2 sparse gather + LIF2 + store; returns (anyS1|anyS2) for quiescence
__device__ __forceinline__ unsigned step_tail(bool s0, bool s1, bool s2, bool s3,
                                              int hl, int shamt,
                                              const float* __restrict__ w2b,
                                              float &m2, bool valid,
                                              float* &po, size_t tstride4) {
    unsigned b0 = __ballot_sync(0xffffffffu, s0);
    unsigned b1 = __ballot_sync(0xffffffffu, s1);
    unsigned b2 = __ballot_sync(0xffffffffu, s2);
    unsigned b3 = __ballot_sync(0xffffffffu, s3);
    unsigned anyS1 = b0 | b1 | b2 | b3;
    float cur2 = 0.0f;
    if (anyS1) {
        unsigned f;
        f = (b0 >> shamt) & 0xffffu;
        while (f) { int i = __ffs(f) - 1; f &= f - 1;
                    if (hl < CDIM) cur2 += w2b[4 * i + 0]; }
        f = (b1 >> shamt) & 0xffffu;
        while (f) { int i = __ffs(f) - 1; f &= f - 1;
                    if (hl < CDIM) cur2 += w2b[4 * i + 1]; }
        f = (b2 >> shamt) & 0xffffu;
        while (f) { int i = __ffs(f) - 1; f &= f - 1;
                    if (hl < CDIM) cur2 += w2b[4 * i + 2]; }
        f = (b3 >> shamt) & 0xffffu;
        while (f) { int i = __ffs(f) - 1; f &= f - 1;
                    if (hl < CDIM) cur2 += w2b[4 * i + 3]; }
    }
    m2 = 0.9f * m2 + cur2;
    bool sp2 = (hl < CDIM) && (m2 > 1.0f);
    if (sp2) { m2 -= 1.0f; if (valid) *po = 1.0f; }
    po = (float*)((char*)po + tstride4);
    unsigned anyS2 = __ballot_sync(0xffffffffu, sp2);
    return anyS1 | anyS2;
}

__global__ __launch_bounds__(256, 5)
void burst_snn_kernel(const float* __restrict__ x,
                      const float* __restrict__ W1,
                      const float* __restrict__ W2,
                      float* __restrict__ out, int B)
{
    __shared__ __align__(16) float sW1[DDIM * W1PAD + W1TAIL];
    __shared__ float sW2[CDIM * W2PAD];
    __shared__ float sPart[4 * W1PAD];
    __shared__ __align__(16) float sCol[64];

    const int tid = threadIdx.x;
    for (int i = tid; i < DDIM * W1PAD + W1TAIL; i += 256) {
        float v = 0.0f;
        if (i < DDIM * W1PAD) {
            int d = i / W1PAD, u = i - d * W1PAD;
            if (u < HDIM) v = W1[u * DDIM + d];
        }
        sW1[i] = v;
    }
    for (int i = tid; i < CDIM * W2PAD; i += 256) {
        int c = i / W2PAD, h = i - c * W2PAD;
        sW2[i] = (h < HDIM) ? W2[c * HDIM + h] : 0.0f;
    }
    __syncthreads();

    // ---- column sums of sW1 (52 padded units x 4 segments) ----
    if (tid < 4 * W1PAD) {
        int u = tid % W1PAD, seg = tid / W1PAD;
        float sa = 0.0f, sb = 0.0f;
        int d = seg;
        for (; d + 4 < DDIM; d += 8) {
            sa += sW1[d * W1PAD + u];
            sb += sW1[(d + 4) * W1PAD + u];
        }
        for (; d < DDIM; d += 4) sa += sW1[d * W1PAD + u];
        sPart[seg * W1PAD + u] = sa + sb;
    }
    __syncthreads();
    if (tid < 64) {
        float v = 0.0f;
        if (tid < W1PAD)
            v = sPart[tid] + sPart[W1PAD + tid] + sPart[2 * W1PAD + tid]
              + sPart[3 * W1PAD + tid];
        sCol[tid] = v;
    }
    __syncthreads();

    const int lane = tid & 31;
    const int hl   = lane & 15;
    const int half = lane >> 4;
    const int b    = (blockIdx.x * 8 + (tid >> 5)) * 2 + half;
    const bool valid = (b < B);

    const float INIT_TH = 0.125f;
    const unsigned long long BETA2 = packx2(0.9f, 0.9f);

    // encoder state: dim d = hl + 16*j
    float r[NGRP], th[NGRP];
    const float* xb = x + (size_t)b * DDIM;
#pragma unroll
    for (int j = 0; j < NGRP; j++) {
        int d = hl + 16 * j;
        r[j]  = (valid && d < DDIM) ? xb[d] : -1.0f;   // -1: dead from start
        th[j] = INIT_TH;
    }

    const bool v01 = (hl < 13), v23 = (hl < 12);

    unsigned long long m01, m23;                 // mem1 packed pairs
    float m2 = 0.0f;
    int cnt = 0;
    unsigned alive = 0xfffu, prevz = 0u, e0 = 0u;

    const char*  wb  = (const char*)sW1 + hl * 16;
    const float* w2b = sW2 + hl * W2PAD;
    const int shamt = lane & 16;
    float* po = out + (size_t)b * CDIM + hl;
    const size_t tstride4 = (size_t)B * CDIM * sizeof(float);

    const ulonglong2 cs = *(const ulonglong2*)((const char*)sCol + hl * 16);
    float g0, g1, g2, g3;
    unpackx2(cs.x, g0, g1); unpackx2(cs.y, g2, g3);

    // ================= t = 0 (complement: ~87% spike) =================
    {
        unsigned long long c01 = 0ull, c23 = 0ull;
#pragma unroll
        for (int j = 0; j < NGRP; j++) {
            bool s = (r[j] >= th[j]);
            unsigned bal = __ballot_sync(0xffffffffu, s);
            cnt += s;
            if (s) { r[j] -= th[j]; th[j] *= 2.0f; }     // else th stays INIT
            if (bal == 0u) e0 |= (1u << j);
            unsigned mh = ((~bal) >> shamt) & ((j == NGRP - 1) ? 0x07ffu : 0xffffu);
            ev_accum(mh, wb + j * (16 * 208), c01, c23);
        }
        float c0, c1, c2, c3;
        unpackx2(c01, c0, c1); unpackx2(c23, c2, c3);
        float a0 = g0 - c0, a1 = g1 - c1, a2 = g2 - c2, a3 = g3 - c3;
        bool s0 = v01 && (a0 > 1.0f), s1 = v01 && (a1 > 1.0f);
        bool s2 = v23 && (a2 > 1.0f), s3 = v23 && (a3 > 1.0f);
        if (s0) a0 -= 1.0f; if (s1) a1 -= 1.0f;
        if (s2) a2 -= 1.0f; if (s3) a3 -= 1.0f;
        m01 = packx2(a0, a1); m23 = packx2(a2, a3);
        step_tail(s0, s1, s2, s3, hl, shamt, w2b, m2, valid, po, tstride4);
    }

    // ================= t = 1 (complement: ~62% spike) =================
    {
        mulx2(m01, BETA2); mulx2(m23, BETA2);
        unsigned long long c01 = 0ull, c23 = 0ull;
#pragma unroll
        for (int j = 0; j < NGRP; j++) {
            bool s = (r[j] >= th[j]);
            unsigned bal = __ballot_sync(0xffffffffu, s);
            cnt += s;
            if (s) { r[j] -= th[j]; th[j] *= 2.0f; }
            else   { th[j] = INIT_TH; }
            if (bal == 0u) prevz |= (1u << j);           // empty at t=1
            unsigned mh = ((~bal) >> shamt) & ((j == NGRP - 1) ? 0x07ffu : 0xffffu);
            ev_accum(mh, wb + j * (16 * 208), c01, c23);
        }
        // dead if empty at both t0 and t1 (th reset at t0 => t1 test was exact)
        alive &= ~(e0 & prevz);
        float a0, a1, a2, a3, c0, c1, c2, c3;
        unpackx2(m01, a0, a1); unpackx2(m23, a2, a3);
        unpackx2(c01, c0, c1); unpackx2(c23, c2, c3);
        a0 += g0 - c0; a1 += g1 - c1; a2 += g2 - c2; a3 += g3 - c3;
        bool s0 = v01 && (a0 > 1.0f), s1 = v01 && (a1 > 1.0f);
        bool s2 = v23 && (a2 > 1.0f), s3 = v23 && (a3 > 1.0f);
        if (s0) a0 -= 1.0f; if (s1) a1 -= 1.0f;
        if (s2) a2 -= 1.0f; if (s3) a3 -= 1.0f;
        m01 = packx2(a0, a1); m23 = packx2(a2, a3);
        step_tail(s0, s1, s2, s3, hl, shamt, w2b, m2, valid, po, tstride4);
    }

    // ============ main loop t >= 2 (sparse + prevz exact death) ============
#pragma unroll 1
    for (int t = 2; t < T_STEPS; t++) {
        mulx2(m01, BETA2); mulx2(m23, BETA2);

#pragma unroll
        for (int j = 0; j < NGRP; j++) {
            const unsigned bit = 1u << j;
            if (!(alive & bit)) continue;
            bool s = (r[j] >= th[j]);
            unsigned bal = __ballot_sync(0xffffffffu, s);
            if (bal == 0u) {
                th[j] = INIT_TH;
                // empty twice in a row => all r < 0.125 => silent forever
                if (prevz & bit) alive &= ~bit;
                else prevz |= bit;
                continue;
            }
            prevz &= ~bit;
            cnt += s;
            if (s) { r[j] -= th[j]; th[j] *= 2.0f; }
            else   { th[j] = INIT_TH; }
            unsigned mh = (bal >> shamt) & 0xffffu;
            ev_accum(mh, wb + j * (16 * 208), m01, m23);
        }

        float a0, a1, a2, a3;
        unpackx2(m01, a0, a1); unpackx2(m23, a2, a3);
        bool s0 = v01 && (a0 > 1.0f), s1 = v01 && (a1 > 1.0f);
        bool s2 = v23 && (a2 > 1.0f), s3 = v23 && (a3 > 1.0f);
        if (s0) a0 -= 1.0f; if (s1) a1 -= 1.0f;
        if (s2) a2 -= 1.0f; if (s3) a3 -= 1.0f;
        m01 = packx2(a0, a1); m23 = packx2(a2, a3);

        unsigned any = step_tail(s0, s1, s2, s3, hl, shamt, w2b, m2,
                                 valid, po, tstride4);
        if (alive == 0u && any == 0u) break;     // provably all-zero from here
    }

    // -------- spike counts (exact integer, reduce within half) --------
#pragma unroll
    for (int off = 8; off; off >>= 1)
        cnt += __shfl_xor_sync(0xffffffffu, cnt, off);
    if (valid && hl == 0)
        out[(size_t)T_STEPS * B * CDIM + b] = (float)cnt;
}

extern "C" void kernel_launch(void* const* d_in, const int* in_sizes, int n_in,
                              void* d_out, int out_size)
{
    const float* x  = (const float*)d_in[0];
    const float* W1 = (const float*)d_in[1];
    const float* W2 = (const float*)d_in[2];
    float* out = (float*)d_out;

    int B = in_sizes[0] / DDIM;
    // pre-zero spk_rec [32,B,5] (coalesced memset engine); counts written by kernel
    cudaMemsetAsync(out, 0, (size_t)T_STEPS * B * CDIM * sizeof(float));
    int blocks = (B + 15) / 16;   // 8 warps/block, 2 samples/warp
    burst_snn_kernel<<<blocks, 256>>>(x, W1, W2, out, B);
}

// round 11
// speedup vs baseline: 1.3593x; 1.1155x over previous
#include <cuda_runtime.h>

// BurstSnn: burst encoder + 2-layer LIF SNN, 32 timesteps.
// x [B,187] f32, W1 [50,187] f32, W2 [5,50] f32
// out: spk_rec [32,B,5] f32 then counts [B] f32
//
// KEY: the burst encoder's spike raster depends only on floor(8x) (all
// comparisons are x >= k/8 and all fp subtractions are exact), so the whole
// encoder collapses to an 8-entry pattern LUT; all input spikes end by t=5.
// Two samples/warp (16-lane halves). t0/t1 via complement accumulation
// against a precomputed W1 column sum; t2..t5 sparse events; short LIF tail.
// spk_rec pre-zeroed by cudaMemsetAsync; kernel stores only 1.0s.

#define T_STEPS 32
#define DDIM 187
#define HDIM 50
#define CDIM 5
#define NGRP 12
#define W1PAD 52          // floats per W1 row (208 B, 16B-aligned)
#define W1TAIL 16
#define W2PAD 68          // 272 B rows

// per-bucket spike-time masks, packed byte k = pattern(bucket k)
#define PAT_PACK 0x071B2B0B03050100ull

__device__ __forceinline__ void addx2(unsigned long long &a, unsigned long long b) {
    asm("add.rn.f32x2 %0, %1, %2;" : "=l"(a) : "l"(a), "l"(b));
}
__device__ __forceinline__ void mulx2(unsigned long long &a, unsigned long long b) {
    asm("mul.rn.f32x2 %0, %1, %2;" : "=l"(a) : "l"(a), "l"(b));
}
__device__ __forceinline__ unsigned long long packx2(float lo, float hi) {
    unsigned long long r; asm("mov.b64 %0, {%1,%2};" : "=l"(r) : "f"(lo), "f"(hi)); return r;
}
__device__ __forceinline__ void unpackx2(unsigned long long v, float &lo, float &hi) {
    asm("mov.b64 {%0,%1}, %2;" : "=f"(lo), "=f"(hi) : "l"(v));
}

// pair-unrolled event accumulation over set bits of mh (warp-lockstep loop)
__device__ __forceinline__ void ev_accum(unsigned mh, const char* gb,
                                         unsigned long long &A01,
                                         unsigned long long &A23) {
    while (mh) {
        int i0 = __ffs(mh) - 1; mh &= mh - 1;
        const ulonglong2 w0 = *(const ulonglong2*)(gb + i0 * 208);
        if (mh) {
            int i1 = __ffs(mh) - 1; mh &= mh - 1;
            const ulonglong2 w1 = *(const ulonglong2*)(gb + i1 * 208);
            addx2(A01, w0.x); addx2(A23, w0.y);
            addx2(A01, w1.x); addx2(A23, w1.y);
        } else {
            addx2(A01, w0.x); addx2(A23, w0.y);
        }
    }
}

// layer-2 sparse gather + LIF2 + store; returns (anyS1|anyS2)
__device__ __forceinline__ unsigned step_tail(bool s0, bool s1, bool s2, bool s3,
                                              int hl, int shamt,
                                              const float* __restrict__ w2b,
                                              float &m2, bool valid,
                                              float* &po, size_t tstride4) {
    unsigned b0 = __ballot_sync(0xffffffffu, s0);
    unsigned b1 = __ballot_sync(0xffffffffu, s1);
    unsigned b2 = __ballot_sync(0xffffffffu, s2);
    unsigned b3 = __ballot_sync(0xffffffffu, s3);
    unsigned anyS1 = b0 | b1 | b2 | b3;
    float cur2 = 0.0f;
    if (anyS1) {
        unsigned f;
        f = (b0 >> shamt) & 0xffffu;
        while (f) { int i = __ffs(f) - 1; f &= f - 1;
                    if (hl < CDIM) cur2 += w2b[4 * i + 0]; }
        f = (b1 >> shamt) & 0xffffu;
        while (f) { int i = __ffs(f) - 1; f &= f - 1;
                    if (hl < CDIM) cur2 += w2b[4 * i + 1]; }
        f = (b2 >> shamt) & 0xffffu;
        while (f) { int i = __ffs(f) - 1; f &= f - 1;
                    if (hl < CDIM) cur2 += w2b[4 * i + 2]; }
        f = (b3 >> shamt) & 0xffffu;
        while (f) { int i = __ffs(f) - 1; f &= f - 1;
                    if (hl < CDIM) cur2 += w2b[4 * i + 3]; }
    }
    m2 = 0.9f * m2 + cur2;
    bool sp2 = (hl < CDIM) && (m2 > 1.0f);
    if (sp2) { m2 -= 1.0f; if (valid) *po = 1.0f; }
    po = (float*)((char*)po + tstride4);
    unsigned anyS2 = __ballot_sync(0xffffffffu, sp2);
    return anyS1 | anyS2;
}

__global__ __launch_bounds__(256, 5)
void burst_snn_kernel(const float* __restrict__ x,
                      const float* __restrict__ W1,
                      const float* __restrict__ W2,
                      float* __restrict__ out, int B)
{
    __shared__ __align__(16) float sW1[DDIM * W1PAD + W1TAIL];
    __shared__ float sW2[CDIM * W2PAD];
    __shared__ float sPart[4 * W1PAD];
    __shared__ __align__(16) float sCol[64];

    const int tid = threadIdx.x;
    for (int i = tid; i < DDIM * W1PAD + W1TAIL; i += 256) {
        float v = 0.0f;
        if (i < DDIM * W1PAD) {
            int d = i / W1PAD, u = i - d * W1PAD;
            if (u < HDIM) v = W1[u * DDIM + d];
        }
        sW1[i] = v;
    }
    for (int i = tid; i < CDIM * W2PAD; i += 256) {
        int c = i / W2PAD, h = i - c * W2PAD;
        sW2[i] = (h < HDIM) ? W2[c * HDIM + h] : 0.0f;
    }
    __syncthreads();

    // ---- column sums of sW1 ----
    if (tid < 4 * W1PAD) {
        int u = tid % W1PAD, seg = tid / W1PAD;
        float sa = 0.0f, sb = 0.0f;
        int d = seg;
        for (; d + 4 < DDIM; d += 8) {
            sa += sW1[d * W1PAD + u];
            sb += sW1[(d + 4) * W1PAD + u];
        }
        for (; d < DDIM; d += 4) sa += sW1[d * W1PAD + u];
        sPart[seg * W1PAD + u] = sa + sb;
    }
    __syncthreads();
    if (tid < 64) {
        float v = 0.0f;
        if (tid < W1PAD)
            v = sPart[tid] + sPart[W1PAD + tid] + sPart[2 * W1PAD + tid]
              + sPart[3 * W1PAD + tid];
        sCol[tid] = v;
    }
    __syncthreads();

    const int lane = tid & 31;
    const int hl   = lane & 15;
    const int half = lane >> 4;
    const int b    = (blockIdx.x * 8 + (tid >> 5)) * 2 + half;
    const bool valid = (b < B);

    const unsigned long long BETA2 = packx2(0.9f, 0.9f);

    // ---- encoder LUT: spike pattern per dim (d = hl + 16*j) ----
    unsigned pat[NGRP];
    int cnt = 0;
    const float* xb = x + (size_t)b * DDIM;
#pragma unroll
    for (int j = 0; j < NGRP; j++) {
        int d = hl + 16 * j;
        unsigned p = 0u;
        if (valid && d < DDIM) {
            unsigned bucket = (unsigned)(xb[d] * 8.0f);     // exact: x in [0,1)
            p = (unsigned)((PAT_PACK >> (bucket * 8)) & 0xffu);
        }
        pat[j] = p;
        cnt += __popc(p);
    }

    const bool v01 = (hl < 13), v23 = (hl < 12);

    unsigned long long m01, m23;                 // mem1 packed pairs
    float m2 = 0.0f;

    const char*  wb  = (const char*)sW1 + hl * 16;
    const float* w2b = sW2 + hl * W2PAD;
    const int shamt = lane & 16;
    float* po = out + (size_t)b * CDIM + hl;
    const size_t tstride4 = (size_t)B * CDIM * sizeof(float);

    const ulonglong2 cs = *(const ulonglong2*)((const char*)sCol + hl * 16);
    float g0, g1, g2, g3;
    unpackx2(cs.x, g0, g1); unpackx2(cs.y, g2, g3);

    // ================= t = 0 (complement; 87.5% spike) =================
    {
        unsigned long long c01 = 0ull, c23 = 0ull;
#pragma unroll
        for (int j = 0; j < NGRP; j++) {
            unsigned bal = __ballot_sync(0xffffffffu, (pat[j] & 1u) != 0u);
            unsigned mh = ((~bal) >> shamt) & ((j == NGRP - 1) ? 0x07ffu : 0xffffu);
            ev_accum(mh, wb + j * (16 * 208), c01, c23);
        }
        float c0, c1, c2, c3;
        unpackx2(c01, c0, c1); unpackx2(c23, c2, c3);
        float a0 = g0 - c0, a1 = g1 - c1, a2 = g2 - c2, a3 = g3 - c3;
        bool s0 = v01 && (a0 > 1.0f), s1 = v01 && (a1 > 1.0f);
        bool s2 = v23 && (a2 > 1.0f), s3 = v23 && (a3 > 1.0f);
        if (s0) a0 -= 1.0f; if (s1) a1 -= 1.0f;
        if (s2) a2 -= 1.0f; if (s3) a3 -= 1.0f;
        m01 = packx2(a0, a1); m23 = packx2(a2, a3);
        step_tail(s0, s1, s2, s3, hl, shamt, w2b, m2, valid, po, tstride4);
    }

    // ================= t = 1 (complement; 62.5% spike) =================
    {
        mulx2(m01, BETA2); mulx2(m23, BETA2);
        unsigned long long c01 = 0ull, c23 = 0ull;
#pragma unroll
        for (int j = 0; j < NGRP; j++) {
            unsigned bal = __ballot_sync(0xffffffffu, (pat[j] & 2u) != 0u);
            unsigned mh = ((~bal) >> shamt) & ((j == NGRP - 1) ? 0x07ffu : 0xffffu);
            ev_accum(mh, wb + j * (16 * 208), c01, c23);
        }
        float a0, a1, a2, a3, c0, c1, c2, c3;
        unpackx2(m01, a0, a1); unpackx2(m23, a2, a3);
        unpackx2(c01, c0, c1); unpackx2(c23, c2, c3);
        a0 += g0 - c0; a1 += g1 - c1; a2 += g2 - c2; a3 += g3 - c3;
        bool s0 = v01 && (a0 > 1.0f), s1 = v01 && (a1 > 1.0f);
        bool s2 = v23 && (a2 > 1.0f), s3 = v23 && (a3 > 1.0f);
        if (s0) a0 -= 1.0f; if (s1) a1 -= 1.0f;
        if (s2) a2 -= 1.0f; if (s3) a3 -= 1.0f;
        m01 = packx2(a0, a1); m23 = packx2(a2, a3);
        step_tail(s0, s1, s2, s3, hl, shamt, w2b, m2, valid, po, tstride4);
    }

    // ============ t = 2..5 (sparse; 25/37.5/12.5/12.5% spike) ============
#pragma unroll
    for (int t = 2; t < 6; t++) {
        mulx2(m01, BETA2); mulx2(m23, BETA2);
        const unsigned bit = 1u << t;
#pragma unroll
        for (int j = 0; j < NGRP; j++) {
            unsigned bal = __ballot_sync(0xffffffffu, (pat[j] & bit) != 0u);
            if (bal) {
                unsigned mh = (bal >> shamt) & 0xffffu;
                ev_accum(mh, wb + j * (16 * 208), m01, m23);
            }
        }
        float a0, a1, a2, a3;
        unpackx2(m01, a0, a1); unpackx2(m23, a2, a3);
        bool s0 = v01 && (a0 > 1.0f), s1 = v01 && (a1 > 1.0f);
        bool s2 = v23 && (a2 > 1.0f), s3 = v23 && (a3 > 1.0f);
        if (s0) a0 -= 1.0f; if (s1) a1 -= 1.0f;
        if (s2) a2 -= 1.0f; if (s3) a3 -= 1.0f;
        m01 = packx2(a0, a1); m23 = packx2(a2, a3);
        step_tail(s0, s1, s2, s3, hl, shamt, w2b, m2, valid, po, tstride4);
    }

    // ============ tail t >= 6: encoder silent, LIF decay only ============
#pragma unroll 1
    for (int t = 6; t < T_STEPS; t++) {
        mulx2(m01, BETA2); mulx2(m23, BETA2);
        float a0, a1, a2, a3;
        unpackx2(m01, a0, a1); unpackx2(m23, a2, a3);
        bool s0 = v01 && (a0 > 1.0f), s1 = v01 && (a1 > 1.0f);
        bool s2 = v23 && (a2 > 1.0f), s3 = v23 && (a3 > 1.0f);
        if (s0) a0 -= 1.0f; if (s1) a1 -= 1.0f;
        if (s2) a2 -= 1.0f; if (s3) a3 -= 1.0f;
        m01 = packx2(a0, a1); m23 = packx2(a2, a3);
        unsigned any = step_tail(s0, s1, s2, s3, hl, shamt, w2b, m2,
                                 valid, po, tstride4);
        if (any == 0u) break;    // membranes <= 1, only decay: all zero ahead
    }

    // ---- spike counts (closed form; reduce within 16-lane half) ----
#pragma unroll
    for (int off = 8; off; off >>= 1)
        cnt += __shfl_xor_sync(0xffffffffu, cnt, off);
    if (valid && hl == 0)
        out[(size_t)T_STEPS * B * CDIM + b] = (float)cnt;
}

extern "C" void kernel_launch(void* const* d_in, const int* in_sizes, int n_in,
                              void* d_out, int out_size)
{
    const float* x  = (const float*)d_in[0];
    const float* W1 = (const float*)d_in[1];
    const float* W2 = (const float*)d_in[2];
    float* out = (float*)d_out;

    int B = in_sizes[0] / DDIM;
    // pre-zero spk_rec [32,B,5]; counts written by kernel
    cudaMemsetAsync(out, 0, (size_t)T_STEPS * B * CDIM * sizeof(float));
    int blocks = (B + 15) / 16;   // 8 warps/block, 2 samples/warp
    burst_snn_kernel<<<blocks, 256>>>(x, W1, W2, out, B);
}